// round 2
// baseline (speedup 1.0000x reference)
#include <cuda_runtime.h>
#include <cuda_bf16.h>
#include <cstdint>

// Fixed problem shape (from reference): N=100000, E=1250000, IN=6, HID=64.
#define NMAX 100352
#define HID 64

// Scratch (device globals: allocation-free rule). 16B-aligned for float4 / red.v4.
__device__ __align__(16) float g_deg[NMAX];
__device__ __align__(16) float g_dis[NMAX];
__device__ __align__(16) float g_hs [NMAX * HID];   // pre-scaled features h*dis (current layer)
__device__ __align__(16) float g_agg[NMAX * HID];   // aggregation buffer (init = hs => self-loop)
__device__ __align__(16) float g_h  [NMAX * HID];   // post-layer-1 node features
__device__ __align__(16) float g_gsum[HID];         // readout column sums
__device__ int g_is64;                              // edge_index dtype flag

// ---------------------------------------------------------------- dtype detect
// int64 little-endian data viewed as int32 has every odd word == 0 (values < 2^31).
// Random int32 indices in [0,1e5) make 64 consecutive zeros astronomically unlikely.
__global__ void detect_kernel(const int* __restrict__ ei32) {
    if (threadIdx.x == 0) {
        int is64 = 1;
        for (int k = 1; k < 128; k += 2)
            if (ei32[k] != 0) { is64 = 0; break; }
        g_is64 = is64;
    }
}

// ---------------------------------------------------------------- zero
__global__ void zero_kernel(int n) {
    int i = blockIdx.x * blockDim.x + threadIdx.x;
    if (i < n)   g_deg[i]  = 0.0f;
    if (i < HID) g_gsum[i] = 0.0f;
}

// ---------------------------------------------------------------- degree
__global__ void deg_kernel(const int* __restrict__ ei32, int E) {
    int e = blockIdx.x * blockDim.x + threadIdx.x;
    if (e < E) {
        int dst = g_is64 ? ei32[2 * (E + e)] : ei32[E + e];
        atomicAdd(&g_deg[dst], 1.0f);
    }
}

__global__ void dis_kernel(int n) {
    int i = blockIdx.x * blockDim.x + threadIdx.x;
    if (i < n) g_dis[i] = rsqrtf(g_deg[i] + 1.0f);
}

// ---------------------------------------------------------------- layer-1 GEMM (K=6)
// block = 256 threads = 4 nodes x 64 outputs
__global__ void h1_kernel(const float* __restrict__ x, const float* __restrict__ W1, int n) {
    __shared__ float sW[6 * HID];
    __shared__ float sx[4 * 6];
    int tid = threadIdx.x;
    if (tid < 6 * HID) sW[tid] = W1[tid];
    int base = blockIdx.x * 4;
    if (tid < 24) {
        int r = tid / 6, c = tid % 6;
        sx[tid] = (base + r < n) ? x[(size_t)(base + r) * 6 + c] : 0.0f;
    }
    __syncthreads();
    int j = tid & 63, nl = tid >> 6;
    int row = base + nl;
    if (row < n) {
        float acc = 0.0f;
#pragma unroll
        for (int k = 0; k < 6; ++k) acc += sx[nl * 6 + k] * sW[k * HID + j];
        float v = acc * g_dis[row];
        size_t idx = (size_t)row * HID + j;
        g_hs[idx]  = v;
        g_agg[idx] = v;   // self-loop term
    }
}

// ---------------------------------------------------------------- edge scatter
// 16 threads per edge, each handles one float4 chunk. Pure sum: agg[dst] += hs[src].
__global__ void edge_kernel(const int* __restrict__ ei32, int E) {
    unsigned t = blockIdx.x * blockDim.x + threadIdx.x;
    int e = t >> 4;
    if (e >= E) return;
    int c = t & 15;
    int src, dst;
    if (g_is64) {
        src = __ldg(&ei32[2 * e]);
        dst = __ldg(&ei32[2 * (E + e)]);
    } else {
        src = __ldg(&ei32[e]);
        dst = __ldg(&ei32[E + e]);
    }
    float4 v = __ldg(((const float4*)(g_hs + (size_t)src * HID)) + c);
    float* p = g_agg + (size_t)dst * HID + c * 4;
    asm volatile("red.global.add.v4.f32 [%0], {%1,%2,%3,%4};"
                 :: "l"(p), "f"(v.x), "f"(v.y), "f"(v.z), "f"(v.w) : "memory");
}

// ---------------------------------------------------------------- post layer-1: relu(dis*agg + b1)
__global__ void post1_kernel(const float* __restrict__ b1, int n) {
    int idx = blockIdx.x * blockDim.x + threadIdx.x;
    if (idx < n * HID) {
        int i = idx >> 6, j = idx & 63;
        float v = g_dis[i] * g_agg[idx] + b1[j];
        g_h[idx] = fmaxf(v, 0.0f);
    }
}

// ---------------------------------------------------------------- layer-2 GEMM (64x64)
// block = 256 threads; tile = 64 nodes x 64 outs; each thread 4x4 register block.
__global__ void h2_kernel(const float* __restrict__ W2, int n) {
    __shared__ float sH[64 * 64];
    __shared__ float sW[64 * 64];
    int tid = threadIdx.x;
    int base = blockIdx.x * 64;
    // load W2 (16 KB)
    for (int i = tid; i < 64 * 16; i += 256)
        ((float4*)sW)[i] = ((const float4*)W2)[i];
    // load H tile (16 KB) with bounds
    for (int i = tid; i < 64 * 16; i += 256) {
        int r = i >> 4, c4 = i & 15;
        float4 v = make_float4(0, 0, 0, 0);
        if (base + r < n) v = ((const float4*)(g_h + (size_t)(base + r) * HID))[c4];
        ((float4*)sH)[i] = v;
    }
    __syncthreads();
    int tx = tid & 15;   // outs tx*4 .. tx*4+3
    int ty = tid >> 4;   // nodes ty*4 .. ty*4+3
    float acc[4][4] = {};
#pragma unroll 8
    for (int k = 0; k < 64; ++k) {
        float4 w = ((const float4*)(sW + k * 64))[tx];
        float xv[4];
#pragma unroll
        for (int r = 0; r < 4; ++r) xv[r] = sH[(ty * 4 + r) * 64 + k];
#pragma unroll
        for (int r = 0; r < 4; ++r) {
            acc[r][0] += xv[r] * w.x;
            acc[r][1] += xv[r] * w.y;
            acc[r][2] += xv[r] * w.z;
            acc[r][3] += xv[r] * w.w;
        }
    }
#pragma unroll
    for (int r = 0; r < 4; ++r) {
        int row = base + ty * 4 + r;
        if (row < n) {
            float d = g_dis[row];
            float4 v = make_float4(acc[r][0] * d, acc[r][1] * d, acc[r][2] * d, acc[r][3] * d);
            ((float4*)(g_hs  + (size_t)row * HID))[tx] = v;
            ((float4*)(g_agg + (size_t)row * HID))[tx] = v;   // self-loop
        }
    }
}

// ---------------------------------------------------------------- readout: gsum[j] = sum_i dis[i]*agg[i][j]
__global__ void colsum_kernel(int n) {
    __shared__ float s[256];
    int tid = threadIdx.x;
    int j  = tid & 63;
    int rw = tid >> 6;   // 0..3
    float acc = 0.0f;
    for (int i = blockIdx.x * 4 + rw; i < n; i += gridDim.x * 4)
        acc += g_dis[i] * g_agg[(size_t)i * HID + j];
    s[tid] = acc;
    __syncthreads();
    if (tid < 64) {
        float v = s[tid] + s[tid + 64] + s[tid + 128] + s[tid + 192];
        atomicAdd(&g_gsum[tid], v);
    }
}

// ---------------------------------------------------------------- final: sigmoid(mean(g) . Wfc + bfc)
__global__ void final_kernel(const float* __restrict__ b2, const float* __restrict__ Wfc,
                             const float* __restrict__ bfc, float* __restrict__ out, int n) {
    __shared__ float s[HID];
    int j = threadIdx.x;   // 64 threads
    float g = g_gsum[j] / (float)n + b2[j];
    s[j] = g * Wfc[j];
    __syncthreads();
    if (j < 32) {
        float v = s[j] + s[j + 32];
#pragma unroll
        for (int o = 16; o; o >>= 1) v += __shfl_down_sync(0xffffffff, v, o);
        if (j == 0) out[0] = 1.0f / (1.0f + expf(-(v + bfc[0])));
    }
}

// ================================================================ launch
extern "C" void kernel_launch(void* const* d_in, const int* in_sizes, int n_in,
                              void* d_out, int out_size) {
    const float* x   = (const float*)d_in[0];
    const int*   ei  = (const int*)d_in[1];   // int32 OR int64 (auto-detected on device)
    const float* W1  = (const float*)d_in[2];
    const float* b1  = (const float*)d_in[3];
    const float* W2  = (const float*)d_in[4];
    const float* b2  = (const float*)d_in[5];
    const float* Wfc = (const float*)d_in[6];
    const float* bfc = (const float*)d_in[7];
    float* out = (float*)d_out;

    int n = in_sizes[0] / 6;      // 100000
    int E = in_sizes[1] / 2;      // 1250000

    detect_kernel<<<1, 32>>>(ei);
    zero_kernel<<<(n + 255) / 256, 256>>>(n);
    deg_kernel<<<(E + 255) / 256, 256>>>(ei, E);
    dis_kernel<<<(n + 255) / 256, 256>>>(n);

    // layer 1
    h1_kernel<<<(n + 3) / 4, 256>>>(x, W1, n);
    {
        long long tot = (long long)E * 16;
        edge_kernel<<<(unsigned)((tot + 255) / 256), 256>>>(ei, E);
    }
    post1_kernel<<<(n * HID + 255) / 256, 256>>>(b1, n);

    // layer 2
    h2_kernel<<<(n + 63) / 64, 256>>>(W2, n);
    {
        long long tot = (long long)E * 16;
        edge_kernel<<<(unsigned)((tot + 255) / 256), 256>>>(ei, E);
    }

    // readout + head
    colsum_kernel<<<512, 256>>>(n);
    final_kernel<<<1, HID>>>(b2, Wfc, bfc, out, n);
}

// round 3
// speedup vs baseline: 1.5681x; 1.5681x over previous
#include <cuda_runtime.h>
#include <cuda_bf16.h>
#include <cstdint>

// Fixed problem shape: N=100000, E=1250000, IN=6, HID=64.
#define NMAX 100352
#define EMAX 1310720
#define HID 64

// ---------------- scratch (device globals; 16B aligned for float4) ----------------
__device__ __align__(16) float g_dis [NMAX];
__device__ __align__(16) float g_hs  [NMAX * HID];  // dis-scaled features of current layer
__device__ __align__(16) float g_h   [NMAX * HID];  // post layer-1 activations
__device__ __align__(16) float g_gsum[HID];
__device__ int g_degi[NMAX];
__device__ int g_off [NMAX + 1];
__device__ int g_cur [NMAX];
__device__ int g_bsum[256];
__device__ int g_boff[256];
__device__ int g_csrc[EMAX];                        // CSR: src ids grouped by dst
__device__ int g_is64;

// ---------------- dtype detect: int64 little-endian => odd words all zero ----------------
__global__ void detect_kernel(const int* __restrict__ ei32) {
    if (threadIdx.x == 0) {
        int is64 = 1;
        for (int k = 1; k < 128; k += 2)
            if (ei32[k] != 0) { is64 = 0; break; }
        g_is64 = is64;
    }
}

__global__ void zero_kernel(int n) {
    int i = blockIdx.x * blockDim.x + threadIdx.x;
    if (i < n)   g_degi[i] = 0;
    if (i < HID) g_gsum[i] = 0.0f;
}

// ---------------- degree count ----------------
__global__ void degcnt_kernel(const int* __restrict__ ei32, int E) {
    int e = blockIdx.x * blockDim.x + threadIdx.x;
    if (e < E) {
        int dst = g_is64 ? __ldg(&ei32[2 * (E + e)]) : __ldg(&ei32[E + e]);
        atomicAdd(&g_degi[dst], 1);
    }
}

// ---------------- 3-stage exclusive scan (tile = 1024) ----------------
__global__ void scanA_kernel(int n) {
    __shared__ int s[1024];
    int t = threadIdx.x;
    int i = blockIdx.x * 1024 + t;
    s[t] = (i < n) ? g_degi[i] : 0;
    __syncthreads();
    for (int o = 512; o; o >>= 1) {
        if (t < o) s[t] += s[t + o];
        __syncthreads();
    }
    if (t == 0) g_bsum[blockIdx.x] = s[0];
}

__global__ void scanB_kernel(int nb, int n) {
    if (threadIdx.x == 0) {
        int r = 0;
        for (int b = 0; b < nb; ++b) { g_boff[b] = r; r += g_bsum[b]; }
        g_off[n] = r;
    }
}

__global__ void scanC_kernel(int n) {
    __shared__ int s[2][1024];
    int t = threadIdx.x;
    int i = blockIdx.x * 1024 + t;
    int v = (i < n) ? g_degi[i] : 0;
    s[0][t] = v;
    __syncthreads();
    int cur = 0;
    for (int o = 1; o < 1024; o <<= 1) {
        int nxt = cur ^ 1;
        s[nxt][t] = s[cur][t] + ((t >= o) ? s[cur][t - o] : 0);
        __syncthreads();
        cur = nxt;
    }
    if (i < n) {
        int off = g_boff[blockIdx.x] + s[cur][t] - v;   // exclusive
        g_off[i] = off;
        g_cur[i] = off;
    }
}

// ---------------- CSR fill ----------------
__global__ void fill_kernel(const int* __restrict__ ei32, int E) {
    int e = blockIdx.x * blockDim.x + threadIdx.x;
    if (e < E) {
        int src, dst;
        if (g_is64) { src = __ldg(&ei32[2 * e]); dst = __ldg(&ei32[2 * (E + e)]); }
        else        { src = __ldg(&ei32[e]);     dst = __ldg(&ei32[E + e]); }
        int p = atomicAdd(&g_cur[dst], 1);
        g_csrc[p] = src;
    }
}

__global__ void dis_kernel(int n) {
    int i = blockIdx.x * blockDim.x + threadIdx.x;
    if (i < n) g_dis[i] = rsqrtf((float)g_degi[i] + 1.0f);
}

// ---------------- layer-1 GEMM (K=6): hs = (x @ W1) * dis ----------------
__global__ void h1_kernel(const float* __restrict__ x, const float* __restrict__ W1, int n) {
    __shared__ float sW[6 * HID];
    __shared__ float sx[4 * 6];
    int tid = threadIdx.x;
    if (tid < 6 * HID) sW[tid] = W1[tid];
    int base = blockIdx.x * 4;
    if (tid < 24) {
        int r = tid / 6, c = tid % 6;
        sx[tid] = (base + r < n) ? x[(size_t)(base + r) * 6 + c] : 0.0f;
    }
    __syncthreads();
    int j = tid & 63, nl = tid >> 6;
    int row = base + nl;
    if (row < n) {
        float acc = 0.0f;
#pragma unroll
        for (int k = 0; k < 6; ++k) acc += sx[nl * 6 + k] * sW[k * HID + j];
        g_hs[(size_t)row * HID + j] = acc * g_dis[row];
    }
}

// ---------------- pull aggregation: 16 threads per dst, each owns one float4 chunk ----
// LAYER 1: g_h[dst] = relu( dis*(acc) + b1 ),   acc includes self (hs[dst])
// LAYER 2: column-reduce dis*acc into g_gsum (graph readout), no materialization
template <int LAYER>
__global__ void pull_kernel(const float* __restrict__ bias, int n) {
    __shared__ float sred[16 * HID];
    int grp  = blockIdx.x * 16 + (threadIdx.x >> 4);
    int lane = threadIdx.x & 15;
    bool valid = grp < n;
    float4 acc = make_float4(0.f, 0.f, 0.f, 0.f);
    if (valid) {
        const float4* rowp = (const float4*)g_hs;
        acc = __ldg(rowp + (size_t)grp * 16 + lane);          // self-loop
        int k = g_off[grp], e = g_off[grp + 1];
        for (; k + 4 <= e; k += 4) {
            int s0 = __ldg(&g_csrc[k]);
            int s1 = __ldg(&g_csrc[k + 1]);
            int s2 = __ldg(&g_csrc[k + 2]);
            int s3 = __ldg(&g_csrc[k + 3]);
            float4 v0 = __ldg(rowp + (size_t)s0 * 16 + lane);
            float4 v1 = __ldg(rowp + (size_t)s1 * 16 + lane);
            float4 v2 = __ldg(rowp + (size_t)s2 * 16 + lane);
            float4 v3 = __ldg(rowp + (size_t)s3 * 16 + lane);
            acc.x += (v0.x + v1.x) + (v2.x + v3.x);
            acc.y += (v0.y + v1.y) + (v2.y + v3.y);
            acc.z += (v0.z + v1.z) + (v2.z + v3.z);
            acc.w += (v0.w + v1.w) + (v2.w + v3.w);
        }
        for (; k < e; ++k) {
            int s0 = __ldg(&g_csrc[k]);
            float4 v = __ldg(rowp + (size_t)s0 * 16 + lane);
            acc.x += v.x; acc.y += v.y; acc.z += v.z; acc.w += v.w;
        }
        float d = g_dis[grp];
        acc.x *= d; acc.y *= d; acc.z *= d; acc.w *= d;
    }
    if (LAYER == 1) {
        if (valid) {
            float4 b = __ldg((const float4*)bias + lane);
            float4 o;
            o.x = fmaxf(acc.x + b.x, 0.f);
            o.y = fmaxf(acc.y + b.y, 0.f);
            o.z = fmaxf(acc.z + b.z, 0.f);
            o.w = fmaxf(acc.w + b.w, 0.f);
            ((float4*)g_h)[(size_t)grp * 16 + lane] = o;
        }
    } else {
        int gl = threadIdx.x >> 4;
        ((float4*)sred)[gl * 16 + lane] = valid ? acc : make_float4(0.f, 0.f, 0.f, 0.f);
        __syncthreads();
        if (threadIdx.x < HID) {
            float v = 0.f;
#pragma unroll
            for (int r = 0; r < 16; ++r) v += sred[r * HID + threadIdx.x];
            atomicAdd(&g_gsum[threadIdx.x], v);
        }
    }
}

// ---------------- layer-2 GEMM (64x64): hs = (g_h @ W2) * dis ----------------
__global__ void h2_kernel(const float* __restrict__ W2, int n) {
    __shared__ float sH[64 * 64];
    __shared__ float sW[64 * 64];
    int tid = threadIdx.x;
    int base = blockIdx.x * 64;
    for (int i = tid; i < 64 * 16; i += 256)
        ((float4*)sW)[i] = ((const float4*)W2)[i];
    for (int i = tid; i < 64 * 16; i += 256) {
        int r = i >> 4, c4 = i & 15;
        float4 v = make_float4(0, 0, 0, 0);
        if (base + r < n) v = ((const float4*)(g_h + (size_t)(base + r) * HID))[c4];
        ((float4*)sH)[i] = v;
    }
    __syncthreads();
    int tx = tid & 15;
    int ty = tid >> 4;
    float acc[4][4] = {};
#pragma unroll 8
    for (int k = 0; k < 64; ++k) {
        float4 w = ((const float4*)(sW + k * 64))[tx];
        float xv[4];
#pragma unroll
        for (int r = 0; r < 4; ++r) xv[r] = sH[(ty * 4 + r) * 64 + k];
#pragma unroll
        for (int r = 0; r < 4; ++r) {
            acc[r][0] += xv[r] * w.x;
            acc[r][1] += xv[r] * w.y;
            acc[r][2] += xv[r] * w.z;
            acc[r][3] += xv[r] * w.w;
        }
    }
#pragma unroll
    for (int r = 0; r < 4; ++r) {
        int row = base + ty * 4 + r;
        if (row < n) {
            float d = g_dis[row];
            float4 v = make_float4(acc[r][0] * d, acc[r][1] * d, acc[r][2] * d, acc[r][3] * d);
            ((float4*)(g_hs + (size_t)row * HID))[tx] = v;
        }
    }
}

// ---------------- final: sigmoid( (gsum/n + b2) . Wfc + bfc ) ----------------
__global__ void final_kernel(const float* __restrict__ b2, const float* __restrict__ Wfc,
                             const float* __restrict__ bfc, float* __restrict__ out, int n) {
    __shared__ float s[HID];
    int j = threadIdx.x;
    float g = g_gsum[j] / (float)n + b2[j];
    s[j] = g * Wfc[j];
    __syncthreads();
    if (j < 32) {
        float v = s[j] + s[j + 32];
#pragma unroll
        for (int o = 16; o; o >>= 1) v += __shfl_down_sync(0xffffffff, v, o);
        if (j == 0) out[0] = 1.0f / (1.0f + expf(-(v + bfc[0])));
    }
}

// ================================================================ launch
extern "C" void kernel_launch(void* const* d_in, const int* in_sizes, int n_in,
                              void* d_out, int out_size) {
    const float* x   = (const float*)d_in[0];
    const int*   ei  = (const int*)d_in[1];   // int32 OR int64 (auto-detected on device)
    const float* W1  = (const float*)d_in[2];
    const float* b1  = (const float*)d_in[3];
    const float* W2  = (const float*)d_in[4];
    const float* b2  = (const float*)d_in[5];
    const float* Wfc = (const float*)d_in[6];
    const float* bfc = (const float*)d_in[7];
    float* out = (float*)d_out;

    int n = in_sizes[0] / 6;      // 100000
    int E = in_sizes[1] / 2;      // 1250000
    int nb = (n + 1023) / 1024;   // scan tiles

    detect_kernel<<<1, 32>>>(ei);
    zero_kernel<<<(n + 255) / 256, 256>>>(n);
    degcnt_kernel<<<(E + 255) / 256, 256>>>(ei, E);
    scanA_kernel<<<nb, 1024>>>(n);
    scanB_kernel<<<1, 32>>>(nb, n);
    scanC_kernel<<<nb, 1024>>>(n);
    fill_kernel<<<(E + 255) / 256, 256>>>(ei, E);
    dis_kernel<<<(n + 255) / 256, 256>>>(n);

    // layer 1
    h1_kernel<<<(n + 3) / 4, 256>>>(x, W1, n);
    pull_kernel<1><<<(n + 15) / 16, 256>>>(b1, n);

    // layer 2 (+ fused readout)
    h2_kernel<<<(n + 63) / 64, 256>>>(W2, n);
    pull_kernel<2><<<(n + 15) / 16, 256>>>(nullptr, n);

    final_kernel<<<1, HID>>>(b2, Wfc, bfc, out, n);
}